// round 2
// baseline (speedup 1.0000x reference)
#include <cuda_runtime.h>
#include <math.h>

#define NPTS 4096
#define DIMS 64
#define MAX_ITERS 44
#define NEGLOGN (-8.317766166719343f) /* -log(4096) */

// ---------------- static device scratch (no allocs allowed) ----------------
__device__ float dCxy[(size_t)NPTS * NPTS];
__device__ float dCyx[(size_t)NPTS * NPTS];
__device__ float dCxx[(size_t)NPTS * NPTS];
__device__ float dCyy[(size_t)NPTS * NPTS];
__device__ float dX2[NPTS];
__device__ float dY2[NPTS];
__device__ float dMinV[DIMS];
__device__ float dMaxV[DIMS];
__device__ float dEps[MAX_ITERS];
__device__ int   dNeps;
// dF[parity][slot][i]: slot 0=f_ba, 1=g_ab, 2=f_aa, 3=g_bb
__device__ float dF[2][4][NPTS];
__device__ float dFin[4][NPTS];

// ---------------- small helpers ----------------
__device__ __forceinline__ void atomicMinFloat(float* addr, float v) {
    int* ai = (int*)addr;
    int old = *ai;
    while (__int_as_float(old) > v) {
        int assumed = old;
        old = atomicCAS(ai, assumed, __float_as_int(v));
        if (old == assumed) break;
    }
}
__device__ __forceinline__ void atomicMaxFloat(float* addr, float v) {
    int* ai = (int*)addr;
    int old = *ai;
    while (__int_as_float(old) < v) {
        int assumed = old;
        old = atomicCAS(ai, assumed, __float_as_int(v));
        if (old == assumed) break;
    }
}

// ---------------- 1) bounding box ----------------
__global__ void minmax_init_k() {
    int t = threadIdx.x;
    if (t < DIMS) { dMinV[t] = INFINITY; dMaxV[t] = -INFINITY; }
}

__global__ void minmax_k(const float* __restrict__ x, const float* __restrict__ y) {
    int t = threadIdx.x;          // 256 threads
    int dim = t & (DIMS - 1);
    int sub = t >> 6;             // 0..3
    float mn = INFINITY, mx = -INFINITY;
    for (int row = blockIdx.x * 4 + sub; row < 2 * NPTS; row += 64 * 4) {
        const float* p = (row < NPTS) ? (x + (size_t)row * DIMS)
                                      : (y + (size_t)(row - NPTS) * DIMS);
        float v = p[dim];
        mn = fminf(mn, v);
        mx = fmaxf(mx, v);
    }
    __shared__ float smn[256], smx[256];
    smn[t] = mn; smx[t] = mx;
    __syncthreads();
    if (t < DIMS) {
        mn = fminf(fminf(smn[t], smn[t + 64]), fminf(smn[t + 128], smn[t + 192]));
        mx = fmaxf(fmaxf(smx[t], smx[t + 64]), fmaxf(smx[t + 128], smx[t + 192]));
        atomicMinFloat(&dMinV[t], mn);
        atomicMaxFloat(&dMaxV[t], mx);
    }
}

// ---------------- 2) squared norms ----------------
__global__ void sq_k(const float* __restrict__ x, const float* __restrict__ y) {
    int row = blockIdx.x;         // 0..8191
    int t = threadIdx.x;          // 64 threads
    const float* p = (row < NPTS) ? (x + (size_t)row * DIMS)
                                  : (y + (size_t)(row - NPTS) * DIMS);
    float v = p[t];
    float s = v * v;
#pragma unroll
    for (int o = 16; o; o >>= 1) s += __shfl_xor_sync(0xffffffffu, s, o);
    __shared__ float sm[2];
    if ((t & 31) == 0) sm[t >> 5] = s;
    __syncthreads();
    if (t == 0) {
        float tot = sm[0] + sm[1];
        if (row < NPTS) dX2[row] = tot; else dY2[row - NPTS] = tot;
    }
}

// ---------------- 3) eps schedule (geomloss epsilon_schedule, P=2) ----------------
__global__ void sched_k() {
    float d2 = 0.f;
    for (int d = 0; d < DIMS; d++) {
        float r = dMaxV[d] - dMinV[d];
        d2 += r * r;
    }
    float diam = sqrtf(d2);
    double start = 2.0 * log((double)diam);
    double stop  = 2.0 * log(0.05);
    double step  = 2.0 * log(0.8);
    double cnt = ceil((stop - start) / step);  // np.arange length
    int n_ar = (cnt > 0.0) ? (int)cnt : 0;
    if (n_ar > MAX_ITERS - 2) n_ar = MAX_ITERS - 2;
    dEps[0] = (float)((double)diam * (double)diam);
    for (int k = 0; k < n_ar; k++) dEps[1 + k] = (float)exp(start + (double)k * step);
    dEps[n_ar + 1] = 0.0025f;
    dNeps = n_ar + 2;
    for (int i = n_ar + 2; i < MAX_ITERS; i++) dEps[i] = 0.0025f;
}

// ---------------- 4) cost matrices: C = 0.5(|a|^2+|b|^2) - a.b ----------------
// 128x128 tile, K=64 in two 32-chunks, 256 threads, 8x8 per thread.
__global__ void __launch_bounds__(256) gemm_cost(const float* __restrict__ x,
                                                 const float* __restrict__ y) {
    int seg  = blockIdx.x >> 10;      // 0: xy, 1: xx, 2: yy
    int tile = blockIdx.x & 1023;
    int bm = tile >> 5, bn = tile & 31;
    const float *A, *B, *a2, *b2;
    float* Cc;
    if (seg == 0)      { A = x; B = y; a2 = dX2; b2 = dY2; Cc = dCxy; }
    else if (seg == 1) { A = x; B = x; a2 = dX2; b2 = dX2; Cc = dCxx; }
    else               { A = y; B = y; a2 = dY2; b2 = dY2; Cc = dCyy; }

    __shared__ float As[32][128];
    __shared__ float Bs[32][128];
    int t = threadIdx.x;
    int m0 = bm * 128, n0 = bn * 128;
    int tm = t >> 4, tn = t & 15;

    float acc[8][8];
#pragma unroll
    for (int i = 0; i < 8; i++)
#pragma unroll
        for (int j = 0; j < 8; j++) acc[i][j] = 0.f;

    for (int kc = 0; kc < 2; kc++) {
        // load 128x32 chunk of A and B (row-major [row][64]) into [k][row]
#pragma unroll
        for (int l = 0; l < 4; l++) {
            int lin = t + l * 256;          // 0..1023
            int r  = lin >> 3;              // row 0..127
            int kq = (lin & 7) << 2;        // k-quad 0..28
            float4 va = *(const float4*)(A + (size_t)(m0 + r) * DIMS + kc * 32 + kq);
            As[kq + 0][r] = va.x; As[kq + 1][r] = va.y;
            As[kq + 2][r] = va.z; As[kq + 3][r] = va.w;
            float4 vb = *(const float4*)(B + (size_t)(n0 + r) * DIMS + kc * 32 + kq);
            Bs[kq + 0][r] = vb.x; Bs[kq + 1][r] = vb.y;
            Bs[kq + 2][r] = vb.z; Bs[kq + 3][r] = vb.w;
        }
        __syncthreads();
#pragma unroll 8
        for (int k = 0; k < 32; k++) {
            float ar[8], br[8];
#pragma unroll
            for (int i = 0; i < 4; i++) {
                ar[i]     = As[k][tm * 4 + i];
                ar[4 + i] = As[k][64 + tm * 4 + i];
                br[i]     = Bs[k][tn * 4 + i];
                br[4 + i] = Bs[k][64 + tn * 4 + i];
            }
#pragma unroll
            for (int i = 0; i < 8; i++)
#pragma unroll
                for (int j = 0; j < 8; j++) acc[i][j] += ar[i] * br[j];
        }
        __syncthreads();
    }

    float b2r[8];
#pragma unroll
    for (int j = 0; j < 4; j++) {
        b2r[j]     = b2[n0 + tn * 4 + j];
        b2r[4 + j] = b2[n0 + 64 + tn * 4 + j];
    }
#pragma unroll
    for (int i = 0; i < 8; i++) {
        int row = m0 + ((i < 4) ? (tm * 4 + i) : (64 + tm * 4 + (i - 4)));
        float ha = 0.5f * a2[row];
        float4 v0, v1;
        v0.x = ha + 0.5f * b2r[0] - acc[i][0];
        v0.y = ha + 0.5f * b2r[1] - acc[i][1];
        v0.z = ha + 0.5f * b2r[2] - acc[i][2];
        v0.w = ha + 0.5f * b2r[3] - acc[i][3];
        v1.x = ha + 0.5f * b2r[4] - acc[i][4];
        v1.y = ha + 0.5f * b2r[5] - acc[i][5];
        v1.z = ha + 0.5f * b2r[6] - acc[i][6];
        v1.w = ha + 0.5f * b2r[7] - acc[i][7];
        *(float4*)(Cc + (size_t)row * NPTS + n0 + tn * 4)      = v0;
        *(float4*)(Cc + (size_t)row * NPTS + n0 + 64 + tn * 4) = v1;
    }
}

// ---------------- 5) transpose Cxy -> Cyx ----------------
__global__ void transpose_k() {
    __shared__ float tile[32][33];
    int bx = blockIdx.x & 127, by = blockIdx.x >> 7;
    int x0 = bx * 32, y0 = by * 32;
    int tx = threadIdx.x, ty = threadIdx.y;  // (32, 8)
#pragma unroll
    for (int j = 0; j < 32; j += 8)
        tile[ty + j][tx] = dCxy[(size_t)(y0 + ty + j) * NPTS + x0 + tx];
    __syncthreads();
#pragma unroll
    for (int j = 0; j < 32; j += 8)
        dCyx[(size_t)(x0 + ty + j) * NPTS + y0 + tx] = tile[tx][ty + j];
}

// ---------------- softmin core: row-wise stabilized LSE ----------------
// u_j = H[j] + c0 - C[row][j];  result (on t==0): m = max u, s = sum exp((u-m)/eps)
template <bool HAS_H>
__device__ __forceinline__ void lse_row(const float* __restrict__ Crow,
                                        const float* __restrict__ Hv,
                                        float c0, float invEps,
                                        float& mOut, float& sOut) {
    int t = threadIdx.x;  // 256
    const float4* C4 = (const float4*)Crow;
    const float4* H4 = (const float4*)Hv;
    float m = -INFINITY, s = 0.f;
#pragma unroll
    for (int kk = 0; kk < 4; kk++) {
        int idx = t + kk * 256;
        float4 c = __ldg(&C4[idx]);
        float u0, u1, u2, u3;
        if (HAS_H) {
            float4 h = __ldg(&H4[idx]);
            u0 = h.x + c0 - c.x; u1 = h.y + c0 - c.y;
            u2 = h.z + c0 - c.z; u3 = h.w + c0 - c.w;
        } else {
            u0 = c0 - c.x; u1 = c0 - c.y; u2 = c0 - c.z; u3 = c0 - c.w;
        }
        float mm = fmaxf(fmaxf(u0, u1), fmaxf(u2, u3));
        if (mm > m) { s *= __expf((m - mm) * invEps); m = mm; }
        s += __expf((u0 - m) * invEps) + __expf((u1 - m) * invEps) +
             __expf((u2 - m) * invEps) + __expf((u3 - m) * invEps);
    }
#pragma unroll
    for (int o = 16; o; o >>= 1) {
        float mo = __shfl_xor_sync(0xffffffffu, m, o);
        float so = __shfl_xor_sync(0xffffffffu, s, o);
        float mn = fmaxf(m, mo);
        s = s * __expf((m - mn) * invEps) + so * __expf((mo - mn) * invEps);
        m = mn;
    }
    __shared__ float smM[8], smS[8];
    if ((t & 31) == 0) { smM[t >> 5] = m; smS[t >> 5] = s; }
    __syncthreads();
    if (t < 8) { m = smM[t]; s = smS[t]; } else { m = -INFINITY; s = 0.f; }
#pragma unroll
    for (int o = 4; o; o >>= 1) {
        float mo = __shfl_xor_sync(0xffffffffu, m, o);
        float so = __shfl_xor_sync(0xffffffffu, s, o);
        float mn = fmaxf(m, mo);
        s = s * __expf((m - mn) * invEps) + so * __expf((mo - mn) * invEps);
        m = mn;
    }
    mOut = m; sOut = s;
}

// seg -> matrix & h-slot: 0: Cxy/g_ab, 1: Cyx/f_ba, 2: Cxx/f_aa, 3: Cyy/g_bb
__device__ __forceinline__ const float* seg_C(int seg) {
    return (seg == 0) ? dCxy : (seg == 1) ? dCyx : (seg == 2) ? dCxx : dCyy;
}
__device__ __forceinline__ int seg_h(int seg) {
    return (seg == 0) ? 1 : (seg == 1) ? 0 : seg;
}

__global__ void __launch_bounds__(256) softmin_init_k() {
    int seg = blockIdx.x >> 12;
    int row = blockIdx.x & (NPTS - 1);
    float eps = dEps[0];
    float invEps = 1.0f / eps;
    float c0 = eps * NEGLOGN;
    float m, s;
    lse_row<false>(seg_C(seg) + (size_t)row * NPTS, nullptr, c0, invEps, m, s);
    if (threadIdx.x == 0)
        dF[0][seg][row] = -(m + eps * __logf(s));
}

__global__ void __launch_bounds__(256) softmin_step_k(int iter) {
    int seg = blockIdx.x >> 12;
    int row = blockIdx.x & (NPTS - 1);
    int src = iter & 1, dst = src ^ 1;
    if (iter >= dNeps) {  // past end of data-dependent schedule: identity copy
        if (threadIdx.x == 0) dF[dst][seg][row] = dF[src][seg][row];
        return;
    }
    float eps = dEps[iter];
    float invEps = 1.0f / eps;
    float c0 = eps * NEGLOGN;
    float m, s;
    lse_row<true>(seg_C(seg) + (size_t)row * NPTS, dF[src][seg_h(seg)], c0, invEps, m, s);
    if (threadIdx.x == 0) {
        float ft = -(m + eps * __logf(s));
        dF[dst][seg][row] = 0.5f * (dF[src][seg][row] + ft);
    }
}

__global__ void __launch_bounds__(256) softmin_final_k() {
    int seg = blockIdx.x >> 12;
    int row = blockIdx.x & (NPTS - 1);
    const int src = MAX_ITERS & 1;  // = 0 (MAX_ITERS even)
    float eps = 0.0025f;            // BLUR**P, data-independent
    float invEps = 1.0f / eps;
    float c0 = eps * NEGLOGN;
    float m, s;
    lse_row<true>(seg_C(seg) + (size_t)row * NPTS, dF[src][seg_h(seg)], c0, invEps, m, s);
    if (threadIdx.x == 0)
        dFin[seg][row] = -(m + eps * __logf(s));
}

// ---------------- final reduction: mean(fba-faa) + mean(gab-gbb) ----------------
__global__ void reduce_k(float* out) {
    int t = threadIdx.x;  // 256
    float s = 0.f;
    for (int i = t; i < NPTS; i += 256)
        s += (dFin[0][i] - dFin[2][i]) + (dFin[1][i] - dFin[3][i]);
#pragma unroll
    for (int o = 16; o; o >>= 1) s += __shfl_xor_sync(0xffffffffu, s, o);
    __shared__ float sm[8];
    if ((t & 31) == 0) sm[t >> 5] = s;
    __syncthreads();
    if (t == 0) {
        float tot = 0.f;
        for (int w = 0; w < 8; w++) tot += sm[w];
        out[0] = tot * (1.0f / NPTS);
    }
}

// ---------------- launch ----------------
extern "C" void kernel_launch(void* const* d_in, const int* in_sizes, int n_in,
                              void* d_out, int out_size) {
    const float* x = (const float*)d_in[0];
    const float* y = (const float*)d_in[1];
    float* out = (float*)d_out;

    minmax_init_k<<<1, 64>>>();
    minmax_k<<<64, 256>>>(x, y);
    sq_k<<<2 * NPTS, 64>>>(x, y);
    sched_k<<<1, 1>>>();
    gemm_cost<<<3 * 1024, 256>>>(x, y);
    transpose_k<<<128 * 128, dim3(32, 8)>>>();

    softmin_init_k<<<4 * NPTS, 256>>>();
    for (int i = 0; i < MAX_ITERS; i++)
        softmin_step_k<<<4 * NPTS, 256>>>(i);
    softmin_final_k<<<4 * NPTS, 256>>>();

    reduce_k<<<1, 256>>>(out);
}

// round 3
// speedup vs baseline: 1.9278x; 1.9278x over previous
#include <cuda_runtime.h>
#include <cuda_fp16.h>
#include <math.h>

#define NPTS 4096
#define DIMS 64
#define MAX_ITERS 44
#define NEGLOGN (-8.317766166719343f) /* -log(4096) */
#define LN2f 0.6931471805599453f
#define INVLN2f 1.4426950408889634f

// ---------------- static device scratch ----------------
__device__ float dCxy[(size_t)NPTS * NPTS];
__device__ float dCxx[(size_t)NPTS * NPTS];
__device__ float dCyy[(size_t)NPTS * NPTS];
__device__ __align__(16) __half hCxy[(size_t)NPTS * NPTS];
__device__ __align__(16) __half hCyx[(size_t)NPTS * NPTS];
__device__ __align__(16) __half hCxx[(size_t)NPTS * NPTS];
__device__ __align__(16) __half hCyy[(size_t)NPTS * NPTS];
// dRmin[0]: row mins of Cxy; [1]: col mins of Cxy (= row mins of Cyx); [2]: Cxx; [3]: Cyy
__device__ float dRmin[4][NPTS];
__device__ float dX2[NPTS];
__device__ float dY2[NPTS];
__device__ float dMinV[DIMS];
__device__ float dMaxV[DIMS];
__device__ float dEps[MAX_ITERS];
__device__ int   dNeps;
// dF[parity][slot][i]: slot 0=f_ba, 1=g_ab, 2=f_aa, 3=g_bb
__device__ float dF[2][4][NPTS];
__device__ float dFin[4][NPTS];

// ---------------- helpers ----------------
__device__ __forceinline__ void atomicMinFloat(float* addr, float v) {
    int* ai = (int*)addr;
    int old = *ai;
    while (__int_as_float(old) > v) {
        int assumed = old;
        old = atomicCAS(ai, assumed, __float_as_int(v));
        if (old == assumed) break;
    }
}
__device__ __forceinline__ void atomicMaxFloat(float* addr, float v) {
    int* ai = (int*)addr;
    int old = *ai;
    while (__int_as_float(old) < v) {
        int assumed = old;
        old = atomicCAS(ai, assumed, __float_as_int(v));
        if (old == assumed) break;
    }
}
__device__ __forceinline__ const __half* seg_M(int s) {
    return (s == 0) ? hCxy : (s == 1) ? hCyx : (s == 2) ? hCxx : hCyy;
}
__device__ __forceinline__ int hslot(int s) {
    return (s == 0) ? 1 : (s == 1) ? 0 : s;
}

// ---------------- 0) init arrays ----------------
__global__ void init_arrays_k() {
    int idx = blockIdx.x * 256 + threadIdx.x;
    if (idx < 4 * NPTS) ((float*)dRmin)[idx] = INFINITY;
    else if (idx < 4 * NPTS + DIMS) dMinV[idx - 4 * NPTS] = INFINITY;
    else if (idx < 4 * NPTS + 2 * DIMS) dMaxV[idx - 4 * NPTS - DIMS] = -INFINITY;
}

// ---------------- 1) bounding box ----------------
__global__ void minmax_k(const float* __restrict__ x, const float* __restrict__ y) {
    int t = threadIdx.x;
    int dim = t & (DIMS - 1);
    int sub = t >> 6;
    float mn = INFINITY, mx = -INFINITY;
    for (int row = blockIdx.x * 4 + sub; row < 2 * NPTS; row += 64 * 4) {
        const float* p = (row < NPTS) ? (x + (size_t)row * DIMS)
                                      : (y + (size_t)(row - NPTS) * DIMS);
        float v = p[dim];
        mn = fminf(mn, v);
        mx = fmaxf(mx, v);
    }
    __shared__ float smn[256], smx[256];
    smn[t] = mn; smx[t] = mx;
    __syncthreads();
    if (t < DIMS) {
        mn = fminf(fminf(smn[t], smn[t + 64]), fminf(smn[t + 128], smn[t + 192]));
        mx = fmaxf(fmaxf(smx[t], smx[t + 64]), fmaxf(smx[t + 128], smx[t + 192]));
        atomicMinFloat(&dMinV[t], mn);
        atomicMaxFloat(&dMaxV[t], mx);
    }
}

// ---------------- 2) squared norms ----------------
__global__ void sq_k(const float* __restrict__ x, const float* __restrict__ y) {
    int row = blockIdx.x;
    int t = threadIdx.x;  // 64
    const float* p = (row < NPTS) ? (x + (size_t)row * DIMS)
                                  : (y + (size_t)(row - NPTS) * DIMS);
    float v = p[t];
    float s = v * v;
#pragma unroll
    for (int o = 16; o; o >>= 1) s += __shfl_xor_sync(0xffffffffu, s, o);
    __shared__ float sm[2];
    if ((t & 31) == 0) sm[t >> 5] = s;
    __syncthreads();
    if (t == 0) {
        float tot = sm[0] + sm[1];
        if (row < NPTS) dX2[row] = tot; else dY2[row - NPTS] = tot;
    }
}

// ---------------- 3) eps schedule (parallel over k) ----------------
__global__ void sched_k() {
    int t = threadIdx.x;  // 64 threads
    float d2 = 0.f;
    for (int d = 0; d < DIMS; d++) {
        float r = dMaxV[d] - dMinV[d];
        d2 += r * r;
    }
    float diam = sqrtf(d2);
    double start = 2.0 * log((double)diam);
    double stop  = 2.0 * log(0.05);
    double step  = 2.0 * log(0.8);
    double cnt = ceil((stop - start) / step);
    int n_ar = (cnt > 0.0) ? (int)cnt : 0;
    if (n_ar > MAX_ITERS - 2) n_ar = MAX_ITERS - 2;
    if (t == 0) { dEps[0] = diam * diam; dNeps = n_ar + 2; }
    if (t >= 1 && t < MAX_ITERS) {
        int k = t - 1;
        dEps[t] = (k < n_ar) ? (float)exp(start + (double)k * step) : 0.0025f;
    }
}

// ---------------- 4) cost matrices + per-row/col mins ----------------
__global__ void __launch_bounds__(256) gemm_cost(const float* __restrict__ x,
                                                 const float* __restrict__ y) {
    int seg  = blockIdx.x >> 10;      // 0: xy, 1: xx, 2: yy
    int tile = blockIdx.x & 1023;
    int bm = tile >> 5, bn = tile & 31;
    const float *A, *B, *a2, *b2;
    float* Cc;
    if (seg == 0)      { A = x; B = y; a2 = dX2; b2 = dY2; Cc = dCxy; }
    else if (seg == 1) { A = x; B = x; a2 = dX2; b2 = dX2; Cc = dCxx; }
    else               { A = y; B = y; a2 = dY2; b2 = dY2; Cc = dCyy; }

    __shared__ float As[32][128];
    __shared__ float Bs[32][128];
    __shared__ float redR[128][16];
    __shared__ float redC[128][16];
    int t = threadIdx.x;
    int m0 = bm * 128, n0 = bn * 128;
    int tm = t >> 4, tn = t & 15;

    float acc[8][8];
#pragma unroll
    for (int i = 0; i < 8; i++)
#pragma unroll
        for (int j = 0; j < 8; j++) acc[i][j] = 0.f;

    for (int kc = 0; kc < 2; kc++) {
#pragma unroll
        for (int l = 0; l < 4; l++) {
            int lin = t + l * 256;
            int r  = lin >> 3;
            int kq = (lin & 7) << 2;
            float4 va = *(const float4*)(A + (size_t)(m0 + r) * DIMS + kc * 32 + kq);
            As[kq + 0][r] = va.x; As[kq + 1][r] = va.y;
            As[kq + 2][r] = va.z; As[kq + 3][r] = va.w;
            float4 vb = *(const float4*)(B + (size_t)(n0 + r) * DIMS + kc * 32 + kq);
            Bs[kq + 0][r] = vb.x; Bs[kq + 1][r] = vb.y;
            Bs[kq + 2][r] = vb.z; Bs[kq + 3][r] = vb.w;
        }
        __syncthreads();
#pragma unroll 8
        for (int k = 0; k < 32; k++) {
            float ar[8], br[8];
#pragma unroll
            for (int i = 0; i < 4; i++) {
                ar[i]     = As[k][tm * 4 + i];
                ar[4 + i] = As[k][64 + tm * 4 + i];
                br[i]     = Bs[k][tn * 4 + i];
                br[4 + i] = Bs[k][64 + tn * 4 + i];
            }
#pragma unroll
            for (int i = 0; i < 8; i++)
#pragma unroll
                for (int j = 0; j < 8; j++) acc[i][j] += ar[i] * br[j];
        }
        __syncthreads();
    }

    float b2r[8];
#pragma unroll
    for (int j = 0; j < 4; j++) {
        b2r[j]     = b2[n0 + tn * 4 + j];
        b2r[4 + j] = b2[n0 + 64 + tn * 4 + j];
    }
    float cmin[8];
#pragma unroll
    for (int j = 0; j < 8; j++) cmin[j] = INFINITY;

#pragma unroll
    for (int i = 0; i < 8; i++) {
        int rl = (i < 4) ? (tm * 4 + i) : (64 + tm * 4 + (i - 4));
        int row = m0 + rl;
        float ha = 0.5f * a2[row];
        float4 v0, v1;
        v0.x = ha + 0.5f * b2r[0] - acc[i][0];
        v0.y = ha + 0.5f * b2r[1] - acc[i][1];
        v0.z = ha + 0.5f * b2r[2] - acc[i][2];
        v0.w = ha + 0.5f * b2r[3] - acc[i][3];
        v1.x = ha + 0.5f * b2r[4] - acc[i][4];
        v1.y = ha + 0.5f * b2r[5] - acc[i][5];
        v1.z = ha + 0.5f * b2r[6] - acc[i][6];
        v1.w = ha + 0.5f * b2r[7] - acc[i][7];
        *(float4*)(Cc + (size_t)row * NPTS + n0 + tn * 4)      = v0;
        *(float4*)(Cc + (size_t)row * NPTS + n0 + 64 + tn * 4) = v1;
        float rm = fminf(fminf(fminf(v0.x, v0.y), fminf(v0.z, v0.w)),
                         fminf(fminf(v1.x, v1.y), fminf(v1.z, v1.w)));
        redR[rl][tn] = rm;
        cmin[0] = fminf(cmin[0], v0.x); cmin[1] = fminf(cmin[1], v0.y);
        cmin[2] = fminf(cmin[2], v0.z); cmin[3] = fminf(cmin[3], v0.w);
        cmin[4] = fminf(cmin[4], v1.x); cmin[5] = fminf(cmin[5], v1.y);
        cmin[6] = fminf(cmin[6], v1.z); cmin[7] = fminf(cmin[7], v1.w);
    }
#pragma unroll
    for (int j = 0; j < 8; j++) {
        int cl = (j < 4) ? (tn * 4 + j) : (64 + tn * 4 + (j - 4));
        redC[cl][tm] = cmin[j];
    }
    __syncthreads();
    if (t < 128) {
        float r = INFINITY, c = INFINITY;
#pragma unroll
        for (int k = 0; k < 16; k++) { r = fminf(r, redR[t][k]); c = fminf(c, redC[t][k]); }
        if (seg == 0) {
            atomicMinFloat(&dRmin[0][m0 + t], r);
            atomicMinFloat(&dRmin[1][n0 + t], c);
        } else if (seg == 1) {
            atomicMinFloat(&dRmin[2][m0 + t], r);
        } else {
            atomicMinFloat(&dRmin[3][m0 + t], r);
        }
    }
}

// ---------------- 5) fp32 -> fp16 (relative to row min) ----------------
__global__ void __launch_bounds__(256) conv_straight_k() {
    int seg3  = blockIdx.x >> 13;     // 0:xy 1:xx 2:yy  (8192 blocks each)
    int local = blockIdx.x & 8191;
    const float* C = (seg3 == 0) ? dCxy : (seg3 == 1) ? dCxx : dCyy;
    __half* H = (seg3 == 0) ? hCxy : (seg3 == 1) ? hCxx : hCyy;
    const float* rmin = (seg3 == 0) ? dRmin[0] : (seg3 == 1) ? dRmin[2] : dRmin[3];
    size_t idx = (size_t)local * 2048 + threadIdx.x * 8;
    int row = (int)(idx >> 12);
    float rm = rmin[row];
    float4 a = *(const float4*)(C + idx);
    float4 b = *(const float4*)(C + idx + 4);
    half2 q0 = __floats2half2_rn(a.x - rm, a.y - rm);
    half2 q1 = __floats2half2_rn(a.z - rm, a.w - rm);
    half2 q2 = __floats2half2_rn(b.x - rm, b.y - rm);
    half2 q3 = __floats2half2_rn(b.z - rm, b.w - rm);
    uint4 o;
    o.x = *(unsigned*)&q0; o.y = *(unsigned*)&q1;
    o.z = *(unsigned*)&q2; o.w = *(unsigned*)&q3;
    *(uint4*)(H + idx) = o;
}

// Cxy (fp32) -> hCyx (fp16, transposed, relative to col-mins of Cxy)
__global__ void conv_trans_k() {
    __shared__ float tile[32][33];
    int bx = blockIdx.x & 127, by = blockIdx.x >> 7;
    int x0 = bx * 32, y0 = by * 32;
    int tx = threadIdx.x, ty = threadIdx.y;  // (32, 8)
#pragma unroll
    for (int j = 0; j < 32; j += 8)
        tile[ty + j][tx] = dCxy[(size_t)(y0 + ty + j) * NPTS + x0 + tx];
    __syncthreads();
#pragma unroll
    for (int j = 0; j < 32; j += 8) {
        int orow = x0 + ty + j;
        float rm = dRmin[1][orow];
        hCyx[(size_t)orow * NPTS + y0 + tx] = __float2half_rn(tile[tx][ty + j] - rm);
    }
}

// ---------------- softmin core: 2 rows per warp, exp2 domain ----------------
// z_j = (H_j + c0 - C_ij) * (1/eps) * INVLN2 ; result: m = max z (warp-uniform), s = sum exp2(z-m)
template <bool HAS_H>
__device__ __forceinline__ void lse_pair(const __half* __restrict__ Mrow0,
                                         const float* __restrict__ Hs,
                                         float negs1,
                                         float& M0o, float& S0o, float& M1o, float& S1o) {
    const unsigned FULL = 0xffffffffu;
    int lane = threadIdx.x & 31;
    const uint4* p0 = (const uint4*)Mrow0;
    const uint4* p1 = (const uint4*)(Mrow0 + NPTS);
    float m0 = -INFINITY, s0 = 0.f, m1 = -INFINITY, s1 = 0.f;
    const float C0Z = NEGLOGN * INVLN2f;
#pragma unroll 4
    for (int c = 0; c < 16; c++) {
        int j8 = c * 32 + lane;            // uint4 index; element j = j8*8
        uint4 a0 = __ldg(&p0[j8]);
        uint4 a1 = __ldg(&p1[j8]);
        float h[8];
        if (HAS_H) {
            float4 hA = *(const float4*)&Hs[j8 * 8];
            float4 hB = *(const float4*)&Hs[j8 * 8 + 4];
            h[0] = hA.x; h[1] = hA.y; h[2] = hA.z; h[3] = hA.w;
            h[4] = hB.x; h[5] = hB.y; h[6] = hB.z; h[7] = hB.w;
        } else {
#pragma unroll
            for (int k = 0; k < 8; k++) h[k] = C0Z;
        }
        float z0[8], z1[8];
        const half2* q0 = (const half2*)&a0;
        const half2* q1 = (const half2*)&a1;
#pragma unroll
        for (int k = 0; k < 4; k++) {
            float2 f0 = __half22float2(q0[k]);
            float2 f1 = __half22float2(q1[k]);
            z0[2 * k]     = fmaf(f0.x, negs1, h[2 * k]);
            z0[2 * k + 1] = fmaf(f0.y, negs1, h[2 * k + 1]);
            z1[2 * k]     = fmaf(f1.x, negs1, h[2 * k]);
            z1[2 * k + 1] = fmaf(f1.y, negs1, h[2 * k + 1]);
        }
        float c0m = fmaxf(fmaxf(fmaxf(z0[0], z0[1]), fmaxf(z0[2], z0[3])),
                          fmaxf(fmaxf(z0[4], z0[5]), fmaxf(z0[6], z0[7])));
        float c1m = fmaxf(fmaxf(fmaxf(z1[0], z1[1]), fmaxf(z1[2], z1[3])),
                          fmaxf(fmaxf(z1[4], z1[5]), fmaxf(z1[6], z1[7])));
        bool sk0 = (c0m - m0) < -64.f;
        bool sk1 = (c1m - m1) < -64.f;
        if (!__all_sync(FULL, sk0)) {
            if (c0m > m0) { s0 *= exp2f(m0 - c0m); m0 = c0m; }
#pragma unroll
            for (int k = 0; k < 8; k++) s0 += exp2f(z0[k] - m0);
        }
        if (!__all_sync(FULL, sk1)) {
            if (c1m > m1) { s1 *= exp2f(m1 - c1m); m1 = c1m; }
#pragma unroll
            for (int k = 0; k < 8; k++) s1 += exp2f(z1[k] - m1);
        }
        if ((c & 3) == 3) {  // periodic warp-max broadcast (keeps skip threshold tight)
            float w = m0;
#pragma unroll
            for (int o = 16; o; o >>= 1) w = fmaxf(w, __shfl_xor_sync(FULL, w, o));
            if (w > m0) { s0 *= exp2f(m0 - w); m0 = w; }
            w = m1;
#pragma unroll
            for (int o = 16; o; o >>= 1) w = fmaxf(w, __shfl_xor_sync(FULL, w, o));
            if (w > m1) { s1 *= exp2f(m1 - w); m1 = w; }
        }
    }
    // m is warp-uniform after c=15 broadcast; just sum s across lanes
#pragma unroll
    for (int o = 16; o; o >>= 1) {
        s0 += __shfl_xor_sync(FULL, s0, o);
        s1 += __shfl_xor_sync(FULL, s1, o);
    }
    M0o = m0; S0o = s0; M1o = m1; S1o = s1;
}

// grid: 4 segs * 256 blocks, 256 threads, 16 rows/block (2 per warp)
__global__ void __launch_bounds__(256) softmin_init_k() {
    int seg = blockIdx.x >> 8;
    int b   = blockIdx.x & 255;
    float eps = dEps[0];
    float negs1 = -(1.f / eps) * INVLN2f;
    float el2 = eps * LN2f;
    int w = threadIdx.x >> 5, lane = threadIdx.x & 31;
    int row0 = b * 16 + w * 2;
    const __half* M = seg_M(seg) + (size_t)row0 * NPTS;
    float m0, s0, m1, s1;
    lse_pair<false>(M, nullptr, negs1, m0, s0, m1, s1);
    if (lane == 0) {
        dF[0][seg][row0]     = dRmin[seg][row0]     - el2 * (m0 + log2f(s0));
        dF[0][seg][row0 + 1] = dRmin[seg][row0 + 1] - el2 * (m1 + log2f(s1));
    }
}

__global__ void __launch_bounds__(256) softmin_step_k(int iter) {
    int seg = blockIdx.x >> 8;
    int b   = blockIdx.x & 255;
    int src = iter & 1, dst = src ^ 1;
    int t = threadIdx.x;
    if (iter >= dNeps) {
        if (t < 16) { int r = b * 16 + t; dF[dst][seg][r] = dF[src][seg][r]; }
        return;
    }
    float eps = dEps[iter];
    float s1f = (1.f / eps) * INVLN2f;
    __shared__ __align__(16) float Hs[NPTS];
    const float* Hv = dF[src][hslot(seg)];
    const float C0Z = NEGLOGN * INVLN2f;
    for (int i = t * 4; i < NPTS; i += 1024) {
        float4 hv = *(const float4*)&Hv[i];
        float4 o;
        o.x = fmaf(hv.x, s1f, C0Z); o.y = fmaf(hv.y, s1f, C0Z);
        o.z = fmaf(hv.z, s1f, C0Z); o.w = fmaf(hv.w, s1f, C0Z);
        *(float4*)&Hs[i] = o;
    }
    __syncthreads();
    int w = t >> 5, lane = t & 31;
    int row0 = b * 16 + w * 2;
    const __half* M = seg_M(seg) + (size_t)row0 * NPTS;
    float m0, s0, m1, s1;
    lse_pair<true>(M, Hs, -s1f, m0, s0, m1, s1);
    if (lane == 0) {
        float el2 = eps * LN2f;
        float ft0 = dRmin[seg][row0]     - el2 * (m0 + log2f(s0));
        float ft1 = dRmin[seg][row0 + 1] - el2 * (m1 + log2f(s1));
        dF[dst][seg][row0]     = 0.5f * (dF[src][seg][row0]     + ft0);
        dF[dst][seg][row0 + 1] = 0.5f * (dF[src][seg][row0 + 1] + ft1);
    }
}

__global__ void __launch_bounds__(256) softmin_final_k() {
    int seg = blockIdx.x >> 8;
    int b   = blockIdx.x & 255;
    const int src = MAX_ITERS & 1;  // = 0
    float eps = 0.0025f;            // BLUR**P
    float s1f = (1.f / eps) * INVLN2f;
    int t = threadIdx.x;
    __shared__ __align__(16) float Hs[NPTS];
    const float* Hv = dF[src][hslot(seg)];
    const float C0Z = NEGLOGN * INVLN2f;
    for (int i = t * 4; i < NPTS; i += 1024) {
        float4 hv = *(const float4*)&Hv[i];
        float4 o;
        o.x = fmaf(hv.x, s1f, C0Z); o.y = fmaf(hv.y, s1f, C0Z);
        o.z = fmaf(hv.z, s1f, C0Z); o.w = fmaf(hv.w, s1f, C0Z);
        *(float4*)&Hs[i] = o;
    }
    __syncthreads();
    int w = t >> 5, lane = t & 31;
    int row0 = b * 16 + w * 2;
    const __half* M = seg_M(seg) + (size_t)row0 * NPTS;
    float m0, s0, m1, s1;
    lse_pair<true>(M, Hs, -s1f, m0, s0, m1, s1);
    if (lane == 0) {
        float el2 = eps * LN2f;
        dFin[seg][row0]     = dRmin[seg][row0]     - el2 * (m0 + log2f(s0));
        dFin[seg][row0 + 1] = dRmin[seg][row0 + 1] - el2 * (m1 + log2f(s1));
    }
}

// ---------------- final reduction ----------------
__global__ void reduce_k(float* out) {
    int t = threadIdx.x;  // 256
    float s = 0.f;
    for (int i = t; i < NPTS; i += 256)
        s += (dFin[0][i] - dFin[2][i]) + (dFin[1][i] - dFin[3][i]);
#pragma unroll
    for (int o = 16; o; o >>= 1) s += __shfl_xor_sync(0xffffffffu, s, o);
    __shared__ float sm[8];
    if ((t & 31) == 0) sm[t >> 5] = s;
    __syncthreads();
    if (t == 0) {
        float tot = 0.f;
        for (int w = 0; w < 8; w++) tot += sm[w];
        out[0] = tot * (1.0f / NPTS);
    }
}

// ---------------- launch ----------------
extern "C" void kernel_launch(void* const* d_in, const int* in_sizes, int n_in,
                              void* d_out, int out_size) {
    const float* x = (const float*)d_in[0];
    const float* y = (const float*)d_in[1];
    float* out = (float*)d_out;

    init_arrays_k<<<65, 256>>>();
    minmax_k<<<64, 256>>>(x, y);
    sq_k<<<2 * NPTS, 64>>>(x, y);
    sched_k<<<1, 64>>>();
    gemm_cost<<<3 * 1024, 256>>>(x, y);
    conv_straight_k<<<3 * 8192, 256>>>();
    conv_trans_k<<<128 * 128, dim3(32, 8)>>>();

    softmin_init_k<<<4 * 256, 256>>>();
    for (int i = 0; i < MAX_ITERS; i++)
        softmin_step_k<<<4 * 256, 256>>>(i);
    softmin_final_k<<<4 * 256, 256>>>();

    reduce_k<<<1, 256>>>(out);
}

// round 6
// speedup vs baseline: 3.1471x; 1.6324x over previous
#include <cuda_runtime.h>
#include <cuda_fp16.h>
#include <math.h>

#define NPTS 4096
#define DIMS 64
#define MAX_ITERS 44
#define NB 512                      /* persistent grid: must stay co-resident */
#define NEGLOGN (-8.317766166719343f) /* -log(4096) */
#define LN2f 0.6931471805599453f
#define INVLN2f 1.4426950408889634f

// ---------------- static device scratch ----------------
__device__ float dCxy[(size_t)NPTS * NPTS];
__device__ float dCxx[(size_t)NPTS * NPTS];
__device__ float dCyy[(size_t)NPTS * NPTS];
__device__ __align__(16) __half hCxy[(size_t)NPTS * NPTS];
__device__ __align__(16) __half hCyx[(size_t)NPTS * NPTS];
__device__ __align__(16) __half hCxx[(size_t)NPTS * NPTS];
__device__ __align__(16) __half hCyy[(size_t)NPTS * NPTS];
__device__ float dRmin[4][NPTS];
__device__ float dX2[NPTS];
__device__ float dY2[NPTS];
__device__ float dMinP[128 * DIMS];
__device__ float dMaxP[128 * DIMS];
__device__ float dEps[MAX_ITERS];
__device__ int   dNeps;
__device__ float dF[2][4][NPTS];
__device__ float dFin[4][NPTS];
__device__ unsigned int dBarCnt;
__device__ volatile unsigned int dBarGen;

// ---------------- helpers ----------------
__device__ __forceinline__ float ex2f_(float x) {
    float r; asm("ex2.approx.ftz.f32 %0, %1;" : "=f"(r) : "f"(x)); return r;
}
__device__ __forceinline__ float lg2f_(float x) {
    float r; asm("lg2.approx.ftz.f32 %0, %1;" : "=f"(r) : "f"(x)); return r;
}
__device__ __forceinline__ void atomicMinFloat(float* addr, float v) {
    int* ai = (int*)addr;
    int old = *ai;
    while (__int_as_float(old) > v) {
        int assumed = old;
        old = atomicCAS(ai, assumed, __float_as_int(v));
        if (old == assumed) break;
    }
}
__device__ __forceinline__ const __half* seg_M(int s) {
    return (s == 0) ? hCxy : (s == 1) ? hCyx : (s == 2) ? hCxx : hCyy;
}
__device__ __forceinline__ int hslot(int s) {
    return (s == 0) ? 1 : (s == 1) ? 0 : s;
}

// ---------------- 1) prep: init dRmin + minmax partials + row norms ----------------
__global__ void __launch_bounds__(256) prep_k(const float* __restrict__ x,
                                              const float* __restrict__ y) {
    int t = threadIdx.x, b = blockIdx.x;  // 128 blocks x 256 threads
    int gi = b * 256 + t;
    if (gi < 4 * NPTS) ((float*)dRmin)[gi] = INFINITY;

    // minmax partials: dim = t&63, sub = t>>6
    int dim = t & 63, sub = t >> 6;
    float mn = INFINITY, mx = -INFINITY;
    for (int row = b * 4 + sub; row < 2 * NPTS; row += 128 * 4) {
        const float* p = (row < NPTS) ? (x + (size_t)row * DIMS)
                                      : (y + (size_t)(row - NPTS) * DIMS);
        float v = p[dim];
        mn = fminf(mn, v); mx = fmaxf(mx, v);
    }
    __shared__ float smn[256], smx[256];
    smn[t] = mn; smx[t] = mx;
    __syncthreads();
    if (t < 64) {
        mn = fminf(fminf(smn[t], smn[t + 64]), fminf(smn[t + 128], smn[t + 192]));
        mx = fmaxf(fmaxf(smx[t], smx[t + 64]), fmaxf(smx[t + 128], smx[t + 192]));
        dMinP[b * 64 + t] = mn;
        dMaxP[b * 64 + t] = mx;
    }

    // squared norms: row = b*64 + t/4, quarter q = t&3 (16 dims each)
    int row = b * 64 + (t >> 2), q = t & 3;
    const float* p = (row < NPTS) ? (x + (size_t)row * DIMS)
                                  : (y + (size_t)(row - NPTS) * DIMS);
    float s = 0.f;
#pragma unroll
    for (int k = 0; k < 4; k++) {
        float4 v = ((const float4*)p)[q * 4 + k];
        s += v.x * v.x + v.y * v.y + v.z * v.z + v.w * v.w;
    }
    s += __shfl_xor_sync(0xffffffffu, s, 1);
    s += __shfl_xor_sync(0xffffffffu, s, 2);
    if (q == 0) {
        if (row < NPTS) dX2[row] = s; else dY2[row - NPTS] = s;
    }
}

// ---------------- 2) minmax finalize + eps schedule ----------------
__global__ void sched_k() {
    int t = threadIdx.x;  // 64 threads
    __shared__ float sr2[64];
    __shared__ float sdiam;
    float mn = INFINITY, mx = -INFINITY;
    for (int b = 0; b < 128; b++) {
        mn = fminf(mn, dMinP[b * 64 + t]);
        mx = fmaxf(mx, dMaxP[b * 64 + t]);
    }
    float r = mx - mn;
    sr2[t] = r * r;
    __syncthreads();
    if (t == 0) {
        float d2 = 0.f;
        for (int d = 0; d < 64; d++) d2 += sr2[d];
        sdiam = sqrtf(d2);
    }
    __syncthreads();
    float diam = sdiam;
    double start = 2.0 * log((double)diam);
    double stop  = 2.0 * log(0.05);
    double step  = 2.0 * log(0.8);
    double cnt = ceil((stop - start) / step);
    int n_ar = (cnt > 0.0) ? (int)cnt : 0;
    if (n_ar > MAX_ITERS - 2) n_ar = MAX_ITERS - 2;
    if (t == 0) { dEps[0] = diam * diam; dNeps = n_ar + 2; dBarCnt = 0; }
    if (t >= 1 && t < MAX_ITERS) {
        int k = t - 1;
        dEps[t] = (k < n_ar) ? (float)exp(start + (double)k * step) : 0.0025f;
    }
}

// ---------------- 3) cost matrices + per-row/col mins ----------------
__global__ void __launch_bounds__(256) gemm_cost(const float* __restrict__ x,
                                                 const float* __restrict__ y) {
    int seg  = blockIdx.x >> 10;
    int tile = blockIdx.x & 1023;
    int bm = tile >> 5, bn = tile & 31;
    const float *A, *B, *a2, *b2;
    float* Cc;
    if (seg == 0)      { A = x; B = y; a2 = dX2; b2 = dY2; Cc = dCxy; }
    else if (seg == 1) { A = x; B = x; a2 = dX2; b2 = dX2; Cc = dCxx; }
    else               { A = y; B = y; a2 = dY2; b2 = dY2; Cc = dCyy; }

    __shared__ float As[32][128];
    __shared__ float Bs[32][128];
    __shared__ float redR[128][16];
    __shared__ float redC[128][16];
    int t = threadIdx.x;
    int m0 = bm * 128, n0 = bn * 128;
    int tm = t >> 4, tn = t & 15;

    float acc[8][8];
#pragma unroll
    for (int i = 0; i < 8; i++)
#pragma unroll
        for (int j = 0; j < 8; j++) acc[i][j] = 0.f;

    for (int kc = 0; kc < 2; kc++) {
#pragma unroll
        for (int l = 0; l < 4; l++) {
            int lin = t + l * 256;
            int r  = lin >> 3;
            int kq = (lin & 7) << 2;
            float4 va = *(const float4*)(A + (size_t)(m0 + r) * DIMS + kc * 32 + kq);
            As[kq + 0][r] = va.x; As[kq + 1][r] = va.y;
            As[kq + 2][r] = va.z; As[kq + 3][r] = va.w;
            float4 vb = *(const float4*)(B + (size_t)(n0 + r) * DIMS + kc * 32 + kq);
            Bs[kq + 0][r] = vb.x; Bs[kq + 1][r] = vb.y;
            Bs[kq + 2][r] = vb.z; Bs[kq + 3][r] = vb.w;
        }
        __syncthreads();
#pragma unroll 8
        for (int k = 0; k < 32; k++) {
            float ar[8], br[8];
#pragma unroll
            for (int i = 0; i < 4; i++) {
                ar[i]     = As[k][tm * 4 + i];
                ar[4 + i] = As[k][64 + tm * 4 + i];
                br[i]     = Bs[k][tn * 4 + i];
                br[4 + i] = Bs[k][64 + tn * 4 + i];
            }
#pragma unroll
            for (int i = 0; i < 8; i++)
#pragma unroll
                for (int j = 0; j < 8; j++) acc[i][j] += ar[i] * br[j];
        }
        __syncthreads();
    }

    float b2r[8];
#pragma unroll
    for (int j = 0; j < 4; j++) {
        b2r[j]     = b2[n0 + tn * 4 + j];
        b2r[4 + j] = b2[n0 + 64 + tn * 4 + j];
    }
    float cmin[8];
#pragma unroll
    for (int j = 0; j < 8; j++) cmin[j] = INFINITY;

#pragma unroll
    for (int i = 0; i < 8; i++) {
        int rl = (i < 4) ? (tm * 4 + i) : (64 + tm * 4 + (i - 4));
        int row = m0 + rl;
        float ha = 0.5f * a2[row];
        float4 v0, v1;
        v0.x = ha + 0.5f * b2r[0] - acc[i][0];
        v0.y = ha + 0.5f * b2r[1] - acc[i][1];
        v0.z = ha + 0.5f * b2r[2] - acc[i][2];
        v0.w = ha + 0.5f * b2r[3] - acc[i][3];
        v1.x = ha + 0.5f * b2r[4] - acc[i][4];
        v1.y = ha + 0.5f * b2r[5] - acc[i][5];
        v1.z = ha + 0.5f * b2r[6] - acc[i][6];
        v1.w = ha + 0.5f * b2r[7] - acc[i][7];
        *(float4*)(Cc + (size_t)row * NPTS + n0 + tn * 4)      = v0;
        *(float4*)(Cc + (size_t)row * NPTS + n0 + 64 + tn * 4) = v1;
        float rm = fminf(fminf(fminf(v0.x, v0.y), fminf(v0.z, v0.w)),
                         fminf(fminf(v1.x, v1.y), fminf(v1.z, v1.w)));
        redR[rl][tn] = rm;
        cmin[0] = fminf(cmin[0], v0.x); cmin[1] = fminf(cmin[1], v0.y);
        cmin[2] = fminf(cmin[2], v0.z); cmin[3] = fminf(cmin[3], v0.w);
        cmin[4] = fminf(cmin[4], v1.x); cmin[5] = fminf(cmin[5], v1.y);
        cmin[6] = fminf(cmin[6], v1.z); cmin[7] = fminf(cmin[7], v1.w);
    }
#pragma unroll
    for (int j = 0; j < 8; j++) {
        int cl = (j < 4) ? (tn * 4 + j) : (64 + tn * 4 + (j - 4));
        redC[cl][tm] = cmin[j];
    }
    __syncthreads();
    if (t < 128) {
        float r = INFINITY, c = INFINITY;
#pragma unroll
        for (int k = 0; k < 16; k++) { r = fminf(r, redR[t][k]); c = fminf(c, redC[t][k]); }
        if (seg == 0) {
            atomicMinFloat(&dRmin[0][m0 + t], r);
            atomicMinFloat(&dRmin[1][n0 + t], c);
        } else if (seg == 1) {
            atomicMinFloat(&dRmin[2][m0 + t], r);
        } else {
            atomicMinFloat(&dRmin[3][m0 + t], r);
        }
    }
}

// ---------------- 4) fp32 -> fp16 (relative to row min) ----------------
__global__ void __launch_bounds__(256) conv_straight_k() {
    int seg3  = blockIdx.x >> 13;
    int local = blockIdx.x & 8191;
    const float* C = (seg3 == 0) ? dCxy : (seg3 == 1) ? dCxx : dCyy;
    __half* H = (seg3 == 0) ? hCxy : (seg3 == 1) ? hCxx : hCyy;
    const float* rmin = (seg3 == 0) ? dRmin[0] : (seg3 == 1) ? dRmin[2] : dRmin[3];
    size_t idx = (size_t)local * 2048 + threadIdx.x * 8;
    int row = (int)(idx >> 12);
    float rm = rmin[row];
    float4 a = *(const float4*)(C + idx);
    float4 b = *(const float4*)(C + idx + 4);
    half2 q0 = __floats2half2_rn(a.x - rm, a.y - rm);
    half2 q1 = __floats2half2_rn(a.z - rm, a.w - rm);
    half2 q2 = __floats2half2_rn(b.x - rm, b.y - rm);
    half2 q3 = __floats2half2_rn(b.z - rm, b.w - rm);
    uint4 o;
    o.x = *(unsigned*)&q0; o.y = *(unsigned*)&q1;
    o.z = *(unsigned*)&q2; o.w = *(unsigned*)&q3;
    *(uint4*)(H + idx) = o;
}

// ---------------- 5) Cxy (fp32) -> hCyx (fp16 transposed, col-min relative) ----------------
__global__ void conv_trans_k() {
    __shared__ float tile[32][33];
    int bx = blockIdx.x & 127, by = blockIdx.x >> 7;
    int x0 = bx * 32, y0 = by * 32;
    int tx = threadIdx.x, ty = threadIdx.y;  // (32, 8)
#pragma unroll
    for (int j = 0; j < 32; j += 8)
        tile[ty + j][tx] = dCxy[(size_t)(y0 + ty + j) * NPTS + x0 + tx];
    __syncthreads();
#pragma unroll
    for (int j = 0; j < 32; j += 8) {
        int orow = x0 + ty + j;
        float rm = dRmin[1][orow];
        hCyx[(size_t)orow * NPTS + y0 + tx] = __float2half_rn(tile[tx][ty + j] - rm);
    }
}

// ---------------- grid barrier (all NB blocks resident by construction) ----------------
__device__ __forceinline__ void grid_barrier() {
    __syncthreads();
    if (threadIdx.x == 0) {
        unsigned gen = dBarGen;
        __threadfence();
        if (atomicAdd(&dBarCnt, 1) == NB - 1) {
            dBarCnt = 0;
            __threadfence();
            dBarGen = gen + 1;
        } else {
            while (dBarGen == gen) __nanosleep(64);
        }
        __threadfence();
    }
    __syncthreads();
}

// ---------------- softmin core: 2 rows per warp, exp2-domain, prefetched ----------------
template <bool HAS_H>
__device__ __forceinline__ void lse_pair(const __half* __restrict__ Mrow0,
                                         const float* __restrict__ Hs,
                                         float negs1,
                                         float& M0o, float& S0o, float& M1o, float& S1o) {
    const unsigned FULL = 0xffffffffu;
    int lane = threadIdx.x & 31;
    const uint4* p0 = (const uint4*)Mrow0 + lane;
    const uint4* p1 = (const uint4*)(Mrow0 + NPTS) + lane;
    float m0 = -INFINITY, s0 = 0.f, m1 = -INFINITY, s1 = 0.f;
    const float C0Z = NEGLOGN * INVLN2f;
    uint4 A0 = __ldg(p0);
    uint4 A1 = __ldg(p1);
    int hIdx = lane * 8;
#pragma unroll 4
    for (int c = 0; c < 16; c++) {
        uint4 a0 = A0, a1 = A1;
        if (c < 15) { p0 += 32; p1 += 32; A0 = __ldg(p0); A1 = __ldg(p1); }
        float h[8];
        if (HAS_H) {
            float4 hA = *(const float4*)&Hs[hIdx];
            float4 hB = *(const float4*)&Hs[hIdx + 4];
            h[0] = hA.x; h[1] = hA.y; h[2] = hA.z; h[3] = hA.w;
            h[4] = hB.x; h[5] = hB.y; h[6] = hB.z; h[7] = hB.w;
        } else {
#pragma unroll
            for (int k = 0; k < 8; k++) h[k] = C0Z;
        }
        hIdx += 256;
        float z0[8], z1[8];
        const half2* q0 = (const half2*)&a0;
        const half2* q1 = (const half2*)&a1;
#pragma unroll
        for (int k = 0; k < 4; k++) {
            float2 f0 = __half22float2(q0[k]);
            float2 f1 = __half22float2(q1[k]);
            z0[2 * k]     = fmaf(f0.x, negs1, h[2 * k]);
            z0[2 * k + 1] = fmaf(f0.y, negs1, h[2 * k + 1]);
            z1[2 * k]     = fmaf(f1.x, negs1, h[2 * k]);
            z1[2 * k + 1] = fmaf(f1.y, negs1, h[2 * k + 1]);
        }
        float c0m = fmaxf(fmaxf(fmaxf(z0[0], z0[1]), fmaxf(z0[2], z0[3])),
                          fmaxf(fmaxf(z0[4], z0[5]), fmaxf(z0[6], z0[7])));
        float c1m = fmaxf(fmaxf(fmaxf(z1[0], z1[1]), fmaxf(z1[2], z1[3])),
                          fmaxf(fmaxf(z1[4], z1[5]), fmaxf(z1[6], z1[7])));
        bool sk0 = (c0m - m0) < -64.f;
        bool sk1 = (c1m - m1) < -64.f;
        if (!__all_sync(FULL, sk0)) {
            if (c0m > m0) { s0 *= ex2f_(m0 - c0m); m0 = c0m; }
            float e0 = ex2f_(z0[0] - m0), e1 = ex2f_(z0[1] - m0);
            float e2 = ex2f_(z0[2] - m0), e3 = ex2f_(z0[3] - m0);
            float e4 = ex2f_(z0[4] - m0), e5 = ex2f_(z0[5] - m0);
            float e6 = ex2f_(z0[6] - m0), e7 = ex2f_(z0[7] - m0);
            s0 += ((e0 + e1) + (e2 + e3)) + ((e4 + e5) + (e6 + e7));
        }
        if (!__all_sync(FULL, sk1)) {
            if (c1m > m1) { s1 *= ex2f_(m1 - c1m); m1 = c1m; }
            float e0 = ex2f_(z1[0] - m1), e1 = ex2f_(z1[1] - m1);
            float e2 = ex2f_(z1[2] - m1), e3 = ex2f_(z1[3] - m1);
            float e4 = ex2f_(z1[4] - m1), e5 = ex2f_(z1[5] - m1);
            float e6 = ex2f_(z1[6] - m1), e7 = ex2f_(z1[7] - m1);
            s1 += ((e0 + e1) + (e2 + e3)) + ((e4 + e5) + (e6 + e7));
        }
        if ((c & 3) == 3) {
            float w = m0;
#pragma unroll
            for (int o = 16; o; o >>= 1) w = fmaxf(w, __shfl_xor_sync(FULL, w, o));
            if (w > m0) { s0 *= ex2f_(m0 - w); m0 = w; }
            w = m1;
#pragma unroll
            for (int o = 16; o; o >>= 1) w = fmaxf(w, __shfl_xor_sync(FULL, w, o));
            if (w > m1) { s1 *= ex2f_(m1 - w); m1 = w; }
        }
    }
#pragma unroll
    for (int o = 16; o; o >>= 1) {
        s0 += __shfl_xor_sync(FULL, s0, o);
        s1 += __shfl_xor_sync(FULL, s1, o);
    }
    M0o = m0; S0o = s0; M1o = m1; S1o = s1;
}

// ---------------- 6) persistent Sinkhorn: init + loop + final + reduce ----------------
__global__ void __launch_bounds__(256, 4) sinkhorn_k(float* __restrict__ out) {
    int bid = blockIdx.x;
    int seg = bid >> 7, bb = bid & 127;   // 128 blocks/seg, 32 rows/block
    int t = threadIdx.x, w = t >> 5, lane = t & 31;
    __shared__ __align__(16) float Hs[NPTS];
    const __half* Mbase = seg_M(seg);
    const float* rmin = dRmin[seg];
    const float C0Z = NEGLOGN * INVLN2f;
    int n = dNeps;

    // ---- init pass: eps0, H = log-weights only ----
    {
        float eps = dEps[0];
        float negs1 = -(1.f / eps) * INVLN2f;
        float el2 = eps * LN2f;
#pragma unroll
        for (int rp = 0; rp < 2; rp++) {
            int row0 = bb * 32 + rp * 16 + w * 2;
            float m0, s0, m1, s1;
            lse_pair<false>(Mbase + (size_t)row0 * NPTS, nullptr, negs1, m0, s0, m1, s1);
            if (lane == 0) {
                dF[0][seg][row0]     = rmin[row0]     - el2 * (m0 + lg2f_(s0));
                dF[0][seg][row0 + 1] = rmin[row0 + 1] - el2 * (m1 + lg2f_(s1));
            }
        }
    }
    grid_barrier();

    // ---- annealing loop: exactly n data-dependent iterations ----
    for (int it = 0; it < n; it++) {
        int src = it & 1, dst = src ^ 1;
        float eps = dEps[it];
        float s1f = (1.f / eps) * INVLN2f;
        const float* Hv = dF[src][hslot(seg)];
        for (int i = t * 4; i < NPTS; i += 1024) {
            float4 hv = *(const float4*)&Hv[i];
            float4 o;
            o.x = fmaf(hv.x, s1f, C0Z); o.y = fmaf(hv.y, s1f, C0Z);
            o.z = fmaf(hv.z, s1f, C0Z); o.w = fmaf(hv.w, s1f, C0Z);
            *(float4*)&Hs[i] = o;
        }
        __syncthreads();
        float el2 = eps * LN2f;
#pragma unroll
        for (int rp = 0; rp < 2; rp++) {
            int row0 = bb * 32 + rp * 16 + w * 2;
            float m0, s0, m1, s1;
            lse_pair<true>(Mbase + (size_t)row0 * NPTS, Hs, -s1f, m0, s0, m1, s1);
            if (lane == 0) {
                float ft0 = rmin[row0]     - el2 * (m0 + lg2f_(s0));
                float ft1 = rmin[row0 + 1] - el2 * (m1 + lg2f_(s1));
                dF[dst][seg][row0]     = 0.5f * (dF[src][seg][row0]     + ft0);
                dF[dst][seg][row0 + 1] = 0.5f * (dF[src][seg][row0 + 1] + ft1);
            }
        }
        grid_barrier();
    }

    // ---- final extrapolation at eps = BLUR^P ----
    {
        int src = n & 1;
        float eps = 0.0025f;
        float s1f = (1.f / eps) * INVLN2f;
        const float* Hv = dF[src][hslot(seg)];
        for (int i = t * 4; i < NPTS; i += 1024) {
            float4 hv = *(const float4*)&Hv[i];
            float4 o;
            o.x = fmaf(hv.x, s1f, C0Z); o.y = fmaf(hv.y, s1f, C0Z);
            o.z = fmaf(hv.z, s1f, C0Z); o.w = fmaf(hv.w, s1f, C0Z);
            *(float4*)&Hs[i] = o;
        }
        __syncthreads();
        float el2 = eps * LN2f;
#pragma unroll
        for (int rp = 0; rp < 2; rp++) {
            int row0 = bb * 32 + rp * 16 + w * 2;
            float m0, s0, m1, s1;
            lse_pair<true>(Mbase + (size_t)row0 * NPTS, Hs, -s1f, m0, s0, m1, s1);
            if (lane == 0) {
                dFin[seg][row0]     = rmin[row0]     - el2 * (m0 + lg2f_(s0));
                dFin[seg][row0 + 1] = rmin[row0 + 1] - el2 * (m1 + lg2f_(s1));
            }
        }
    }
    grid_barrier();

    // ---- reduction by block 0 ----
    if (bid == 0) {
        float s = 0.f;
        for (int i = t; i < NPTS; i += 256)
            s += (dFin[0][i] - dFin[2][i]) + (dFin[1][i] - dFin[3][i]);
#pragma unroll
        for (int o = 16; o; o >>= 1) s += __shfl_xor_sync(0xffffffffu, s, o);
        __shared__ float sm[8];
        if (lane == 0) sm[w] = s;
        __syncthreads();
        if (t == 0) {
            float tot = 0.f;
            for (int k = 0; k < 8; k++) tot += sm[k];
            out[0] = tot * (1.0f / NPTS);
        }
    }
}

// ---------------- launch ----------------
extern "C" void kernel_launch(void* const* d_in, const int* in_sizes, int n_in,
                              void* d_out, int out_size) {
    const float* x = (const float*)d_in[0];
    const float* y = (const float*)d_in[1];
    float* out = (float*)d_out;

    prep_k<<<128, 256>>>(x, y);                       // 1
    sched_k<<<1, 64>>>();                             // 2
    gemm_cost<<<3 * 1024, 256>>>(x, y);               // 3
    conv_straight_k<<<3 * 8192, 256>>>();             // 4
    conv_trans_k<<<128 * 128, dim3(32, 8)>>>();       // 5
    sinkhorn_k<<<NB, 256>>>(out);                     // 6  (ncu -s 5 profiles this)
}

// round 7
// speedup vs baseline: 3.1487x; 1.0005x over previous
#include <cuda_runtime.h>
#include <cuda_fp16.h>
#include <math.h>

#define NPTS 4096
#define DIMS 64
#define MAX_ITERS 44
#define NB 512                      /* persistent grid: must stay co-resident */
#define NEGLOGN (-8.317766166719343f) /* -log(4096) */
#define LN2f 0.6931471805599453f
#define INVLN2f 1.4426950408889634f

// ---------------- static device scratch ----------------
__device__ float dCxy[(size_t)NPTS * NPTS];
__device__ float dCxx[(size_t)NPTS * NPTS];
__device__ float dCyy[(size_t)NPTS * NPTS];
__device__ __align__(16) __half hCxy[(size_t)NPTS * NPTS];
__device__ __align__(16) __half hCyx[(size_t)NPTS * NPTS];
__device__ __align__(16) __half hCxx[(size_t)NPTS * NPTS];
__device__ __align__(16) __half hCyy[(size_t)NPTS * NPTS];
__device__ float dRmin[4][NPTS];
__device__ float dX2[NPTS];
__device__ float dY2[NPTS];
__device__ float dMinP[128 * DIMS];
__device__ float dMaxP[128 * DIMS];
__device__ float dEps[MAX_ITERS];
__device__ int   dNeps;
__device__ float dF[2][4][NPTS];
__device__ float dFin[4][NPTS];
__device__ unsigned int dBarCnt;
__device__ volatile unsigned int dBarGen;

// ---------------- helpers ----------------
__device__ __forceinline__ float ex2f_(float x) {
    float r; asm("ex2.approx.ftz.f32 %0, %1;" : "=f"(r) : "f"(x)); return r;
}
__device__ __forceinline__ float lg2f_(float x) {
    float r; asm("lg2.approx.ftz.f32 %0, %1;" : "=f"(r) : "f"(x)); return r;
}
__device__ __forceinline__ void atomicMinFloat(float* addr, float v) {
    int* ai = (int*)addr;
    int old = *ai;
    while (__int_as_float(old) > v) {
        int assumed = old;
        old = atomicCAS(ai, assumed, __float_as_int(v));
        if (old == assumed) break;
    }
}
__device__ __forceinline__ const __half* seg_M(int s) {
    return (s == 0) ? hCxy : (s == 1) ? hCyx : (s == 2) ? hCxx : hCyy;
}
__device__ __forceinline__ int hslot(int s) {
    return (s == 0) ? 1 : (s == 1) ? 0 : s;
}

// ---------------- 1) prep: init dRmin + minmax partials + row norms ----------------
__global__ void __launch_bounds__(256) prep_k(const float* __restrict__ x,
                                              const float* __restrict__ y) {
    int t = threadIdx.x, b = blockIdx.x;  // 128 blocks x 256 threads
    int gi = b * 256 + t;
    if (gi < 4 * NPTS) ((float*)dRmin)[gi] = INFINITY;

    // minmax partials: dim = t&63, sub = t>>6
    int dim = t & 63, sub = t >> 6;
    float mn = INFINITY, mx = -INFINITY;
    for (int row = b * 4 + sub; row < 2 * NPTS; row += 128 * 4) {
        const float* p = (row < NPTS) ? (x + (size_t)row * DIMS)
                                      : (y + (size_t)(row - NPTS) * DIMS);
        float v = p[dim];
        mn = fminf(mn, v); mx = fmaxf(mx, v);
    }
    __shared__ float smn[256], smx[256];
    smn[t] = mn; smx[t] = mx;
    __syncthreads();
    if (t < 64) {
        mn = fminf(fminf(smn[t], smn[t + 64]), fminf(smn[t + 128], smn[t + 192]));
        mx = fmaxf(fmaxf(smx[t], smx[t + 64]), fmaxf(smx[t + 128], smx[t + 192]));
        dMinP[b * 64 + t] = mn;
        dMaxP[b * 64 + t] = mx;
    }

    // squared norms: row = b*64 + t/4, quarter q = t&3 (16 dims each)
    int row = b * 64 + (t >> 2), q = t & 3;
    const float* p = (row < NPTS) ? (x + (size_t)row * DIMS)
                                  : (y + (size_t)(row - NPTS) * DIMS);
    float s = 0.f;
#pragma unroll
    for (int k = 0; k < 4; k++) {
        float4 v = ((const float4*)p)[q * 4 + k];
        s += v.x * v.x + v.y * v.y + v.z * v.z + v.w * v.w;
    }
    s += __shfl_xor_sync(0xffffffffu, s, 1);
    s += __shfl_xor_sync(0xffffffffu, s, 2);
    if (q == 0) {
        if (row < NPTS) dX2[row] = s; else dY2[row - NPTS] = s;
    }
}

// ---------------- 2) minmax finalize + eps schedule ----------------
__global__ void sched_k() {
    int t = threadIdx.x;  // 64 threads
    __shared__ float sr2[64];
    __shared__ float sdiam;
    float mn = INFINITY, mx = -INFINITY;
    for (int b = 0; b < 128; b++) {
        mn = fminf(mn, dMinP[b * 64 + t]);
        mx = fmaxf(mx, dMaxP[b * 64 + t]);
    }
    float r = mx - mn;
    sr2[t] = r * r;
    __syncthreads();
    if (t == 0) {
        float d2 = 0.f;
        for (int d = 0; d < 64; d++) d2 += sr2[d];
        sdiam = sqrtf(d2);
    }
    __syncthreads();
    float diam = sdiam;
    double start = 2.0 * log((double)diam);
    double stop  = 2.0 * log(0.05);
    double step  = 2.0 * log(0.8);
    double cnt = ceil((stop - start) / step);
    int n_ar = (cnt > 0.0) ? (int)cnt : 0;
    if (n_ar > MAX_ITERS - 2) n_ar = MAX_ITERS - 2;
    if (t == 0) { dEps[0] = diam * diam; dNeps = n_ar + 2; dBarCnt = 0; }
    if (t >= 1 && t < MAX_ITERS) {
        int k = t - 1;
        dEps[t] = (k < n_ar) ? (float)exp(start + (double)k * step) : 0.0025f;
    }
}

// ---------------- 3) cost matrices + per-row/col mins ----------------
__global__ void __launch_bounds__(256) gemm_cost(const float* __restrict__ x,
                                                 const float* __restrict__ y) {
    int seg  = blockIdx.x >> 10;
    int tile = blockIdx.x & 1023;
    int bm = tile >> 5, bn = tile & 31;
    const float *A, *B, *a2, *b2;
    float* Cc;
    if (seg == 0)      { A = x; B = y; a2 = dX2; b2 = dY2; Cc = dCxy; }
    else if (seg == 1) { A = x; B = x; a2 = dX2; b2 = dX2; Cc = dCxx; }
    else               { A = y; B = y; a2 = dY2; b2 = dY2; Cc = dCyy; }

    __shared__ float As[32][128];
    __shared__ float Bs[32][128];
    __shared__ float redR[128][16];
    __shared__ float redC[128][16];
    int t = threadIdx.x;
    int m0 = bm * 128, n0 = bn * 128;
    int tm = t >> 4, tn = t & 15;

    float acc[8][8];
#pragma unroll
    for (int i = 0; i < 8; i++)
#pragma unroll
        for (int j = 0; j < 8; j++) acc[i][j] = 0.f;

    for (int kc = 0; kc < 2; kc++) {
#pragma unroll
        for (int l = 0; l < 4; l++) {
            int lin = t + l * 256;
            int r  = lin >> 3;
            int kq = (lin & 7) << 2;
            float4 va = *(const float4*)(A + (size_t)(m0 + r) * DIMS + kc * 32 + kq);
            As[kq + 0][r] = va.x; As[kq + 1][r] = va.y;
            As[kq + 2][r] = va.z; As[kq + 3][r] = va.w;
            float4 vb = *(const float4*)(B + (size_t)(n0 + r) * DIMS + kc * 32 + kq);
            Bs[kq + 0][r] = vb.x; Bs[kq + 1][r] = vb.y;
            Bs[kq + 2][r] = vb.z; Bs[kq + 3][r] = vb.w;
        }
        __syncthreads();
#pragma unroll 8
        for (int k = 0; k < 32; k++) {
            float ar[8], br[8];
#pragma unroll
            for (int i = 0; i < 4; i++) {
                ar[i]     = As[k][tm * 4 + i];
                ar[4 + i] = As[k][64 + tm * 4 + i];
                br[i]     = Bs[k][tn * 4 + i];
                br[4 + i] = Bs[k][64 + tn * 4 + i];
            }
#pragma unroll
            for (int i = 0; i < 8; i++)
#pragma unroll
                for (int j = 0; j < 8; j++) acc[i][j] += ar[i] * br[j];
        }
        __syncthreads();
    }

    float b2r[8];
#pragma unroll
    for (int j = 0; j < 4; j++) {
        b2r[j]     = b2[n0 + tn * 4 + j];
        b2r[4 + j] = b2[n0 + 64 + tn * 4 + j];
    }
    float cmin[8];
#pragma unroll
    for (int j = 0; j < 8; j++) cmin[j] = INFINITY;

#pragma unroll
    for (int i = 0; i < 8; i++) {
        int rl = (i < 4) ? (tm * 4 + i) : (64 + tm * 4 + (i - 4));
        int row = m0 + rl;
        float ha = 0.5f * a2[row];
        float4 v0, v1;
        v0.x = ha + 0.5f * b2r[0] - acc[i][0];
        v0.y = ha + 0.5f * b2r[1] - acc[i][1];
        v0.z = ha + 0.5f * b2r[2] - acc[i][2];
        v0.w = ha + 0.5f * b2r[3] - acc[i][3];
        v1.x = ha + 0.5f * b2r[4] - acc[i][4];
        v1.y = ha + 0.5f * b2r[5] - acc[i][5];
        v1.z = ha + 0.5f * b2r[6] - acc[i][6];
        v1.w = ha + 0.5f * b2r[7] - acc[i][7];
        *(float4*)(Cc + (size_t)row * NPTS + n0 + tn * 4)      = v0;
        *(float4*)(Cc + (size_t)row * NPTS + n0 + 64 + tn * 4) = v1;
        float rm = fminf(fminf(fminf(v0.x, v0.y), fminf(v0.z, v0.w)),
                         fminf(fminf(v1.x, v1.y), fminf(v1.z, v1.w)));
        redR[rl][tn] = rm;
        cmin[0] = fminf(cmin[0], v0.x); cmin[1] = fminf(cmin[1], v0.y);
        cmin[2] = fminf(cmin[2], v0.z); cmin[3] = fminf(cmin[3], v0.w);
        cmin[4] = fminf(cmin[4], v1.x); cmin[5] = fminf(cmin[5], v1.y);
        cmin[6] = fminf(cmin[6], v1.z); cmin[7] = fminf(cmin[7], v1.w);
    }
#pragma unroll
    for (int j = 0; j < 8; j++) {
        int cl = (j < 4) ? (tn * 4 + j) : (64 + tn * 4 + (j - 4));
        redC[cl][tm] = cmin[j];
    }
    __syncthreads();
    if (t < 128) {
        float r = INFINITY, c = INFINITY;
#pragma unroll
        for (int k = 0; k < 16; k++) { r = fminf(r, redR[t][k]); c = fminf(c, redC[t][k]); }
        if (seg == 0) {
            atomicMinFloat(&dRmin[0][m0 + t], r);
            atomicMinFloat(&dRmin[1][n0 + t], c);
        } else if (seg == 1) {
            atomicMinFloat(&dRmin[2][m0 + t], r);
        } else {
            atomicMinFloat(&dRmin[3][m0 + t], r);
        }
    }
}

// ---------------- 4) fp32 -> fp16 (relative to row min) ----------------
__global__ void __launch_bounds__(256) conv_straight_k() {
    int seg3  = blockIdx.x >> 13;
    int local = blockIdx.x & 8191;
    const float* C = (seg3 == 0) ? dCxy : (seg3 == 1) ? dCxx : dCyy;
    __half* H = (seg3 == 0) ? hCxy : (seg3 == 1) ? hCxx : hCyy;
    const float* rmin = (seg3 == 0) ? dRmin[0] : (seg3 == 1) ? dRmin[2] : dRmin[3];
    size_t idx = (size_t)local * 2048 + threadIdx.x * 8;
    int row = (int)(idx >> 12);
    float rm = rmin[row];
    float4 a = *(const float4*)(C + idx);
    float4 b = *(const float4*)(C + idx + 4);
    half2 q0 = __floats2half2_rn(a.x - rm, a.y - rm);
    half2 q1 = __floats2half2_rn(a.z - rm, a.w - rm);
    half2 q2 = __floats2half2_rn(b.x - rm, b.y - rm);
    half2 q3 = __floats2half2_rn(b.z - rm, b.w - rm);
    uint4 o;
    o.x = *(unsigned*)&q0; o.y = *(unsigned*)&q1;
    o.z = *(unsigned*)&q2; o.w = *(unsigned*)&q3;
    *(uint4*)(H + idx) = o;
}

// ---------------- 5) Cxy (fp32) -> hCyx (fp16 transposed, col-min relative) ----------------
__global__ void conv_trans_k() {
    __shared__ float tile[32][33];
    int bx = blockIdx.x & 127, by = blockIdx.x >> 7;
    int x0 = bx * 32, y0 = by * 32;
    int tx = threadIdx.x, ty = threadIdx.y;  // (32, 8)
#pragma unroll
    for (int j = 0; j < 32; j += 8)
        tile[ty + j][tx] = dCxy[(size_t)(y0 + ty + j) * NPTS + x0 + tx];
    __syncthreads();
#pragma unroll
    for (int j = 0; j < 32; j += 8) {
        int orow = x0 + ty + j;
        float rm = dRmin[1][orow];
        hCyx[(size_t)orow * NPTS + y0 + tx] = __float2half_rn(tile[tx][ty + j] - rm);
    }
}

// ---------------- grid barrier (all NB blocks resident by construction) ----------------
__device__ __forceinline__ void grid_barrier() {
    __syncthreads();
    if (threadIdx.x == 0) {
        unsigned gen = dBarGen;
        __threadfence();
        if (atomicAdd(&dBarCnt, 1) == NB - 1) {
            dBarCnt = 0;
            __threadfence();
            dBarGen = gen + 1;
        } else {
            while (dBarGen == gen) __nanosleep(64);
        }
        __threadfence();
    }
    __syncthreads();
}

// ---------------- softmin core: 2 rows per warp, exp2-domain, prefetched ----------------
template <bool HAS_H>
__device__ __forceinline__ void lse_pair(const __half* __restrict__ Mrow0,
                                         const float* __restrict__ Hs,
                                         float negs1,
                                         float& M0o, float& S0o, float& M1o, float& S1o) {
    const unsigned FULL = 0xffffffffu;
    int lane = threadIdx.x & 31;
    const uint4* p0 = (const uint4*)Mrow0 + lane;
    const uint4* p1 = (const uint4*)(Mrow0 + NPTS) + lane;
    float m0 = -INFINITY, s0 = 0.f, m1 = -INFINITY, s1 = 0.f;
    const float C0Z = NEGLOGN * INVLN2f;
    uint4 A0 = __ldg(p0);
    uint4 A1 = __ldg(p1);
    int hIdx = lane * 8;
#pragma unroll 4
    for (int c = 0; c < 16; c++) {
        uint4 a0 = A0, a1 = A1;
        if (c < 15) { p0 += 32; p1 += 32; A0 = __ldg(p0); A1 = __ldg(p1); }
        float h[8];
        if (HAS_H) {
            float4 hA = *(const float4*)&Hs[hIdx];
            float4 hB = *(const float4*)&Hs[hIdx + 4];
            h[0] = hA.x; h[1] = hA.y; h[2] = hA.z; h[3] = hA.w;
            h[4] = hB.x; h[5] = hB.y; h[6] = hB.z; h[7] = hB.w;
        } else {
#pragma unroll
            for (int k = 0; k < 8; k++) h[k] = C0Z;
        }
        hIdx += 256;
        float z0[8], z1[8];
        const half2* q0 = (const half2*)&a0;
        const half2* q1 = (const half2*)&a1;
#pragma unroll
        for (int k = 0; k < 4; k++) {
            float2 f0 = __half22float2(q0[k]);
            float2 f1 = __half22float2(q1[k]);
            z0[2 * k]     = fmaf(f0.x, negs1, h[2 * k]);
            z0[2 * k + 1] = fmaf(f0.y, negs1, h[2 * k + 1]);
            z1[2 * k]     = fmaf(f1.x, negs1, h[2 * k]);
            z1[2 * k + 1] = fmaf(f1.y, negs1, h[2 * k + 1]);
        }
        float c0m = fmaxf(fmaxf(fmaxf(z0[0], z0[1]), fmaxf(z0[2], z0[3])),
                          fmaxf(fmaxf(z0[4], z0[5]), fmaxf(z0[6], z0[7])));
        float c1m = fmaxf(fmaxf(fmaxf(z1[0], z1[1]), fmaxf(z1[2], z1[3])),
                          fmaxf(fmaxf(z1[4], z1[5]), fmaxf(z1[6], z1[7])));
        bool sk0 = (c0m - m0) < -64.f;
        bool sk1 = (c1m - m1) < -64.f;
        if (!__all_sync(FULL, sk0)) {
            if (c0m > m0) { s0 *= ex2f_(m0 - c0m); m0 = c0m; }
            float e0 = ex2f_(z0[0] - m0), e1 = ex2f_(z0[1] - m0);
            float e2 = ex2f_(z0[2] - m0), e3 = ex2f_(z0[3] - m0);
            float e4 = ex2f_(z0[4] - m0), e5 = ex2f_(z0[5] - m0);
            float e6 = ex2f_(z0[6] - m0), e7 = ex2f_(z0[7] - m0);
            s0 += ((e0 + e1) + (e2 + e3)) + ((e4 + e5) + (e6 + e7));
        }
        if (!__all_sync(FULL, sk1)) {
            if (c1m > m1) { s1 *= ex2f_(m1 - c1m); m1 = c1m; }
            float e0 = ex2f_(z1[0] - m1), e1 = ex2f_(z1[1] - m1);
            float e2 = ex2f_(z1[2] - m1), e3 = ex2f_(z1[3] - m1);
            float e4 = ex2f_(z1[4] - m1), e5 = ex2f_(z1[5] - m1);
            float e6 = ex2f_(z1[6] - m1), e7 = ex2f_(z1[7] - m1);
            s1 += ((e0 + e1) + (e2 + e3)) + ((e4 + e5) + (e6 + e7));
        }
        if ((c & 3) == 3) {
            float w = m0;
#pragma unroll
            for (int o = 16; o; o >>= 1) w = fmaxf(w, __shfl_xor_sync(FULL, w, o));
            if (w > m0) { s0 *= ex2f_(m0 - w); m0 = w; }
            w = m1;
#pragma unroll
            for (int o = 16; o; o >>= 1) w = fmaxf(w, __shfl_xor_sync(FULL, w, o));
            if (w > m1) { s1 *= ex2f_(m1 - w); m1 = w; }
        }
    }
#pragma unroll
    for (int o = 16; o; o >>= 1) {
        s0 += __shfl_xor_sync(FULL, s0, o);
        s1 += __shfl_xor_sync(FULL, s1, o);
    }
    M0o = m0; S0o = s0; M1o = m1; S1o = s1;
}

// ---------------- 6) persistent Sinkhorn: init + loop + final + reduce ----------------
__global__ void __launch_bounds__(256, 4) sinkhorn_k(float* __restrict__ out) {
    int bid = blockIdx.x;
    int seg = bid >> 7, bb = bid & 127;   // 128 blocks/seg, 32 rows/block
    int t = threadIdx.x, w = t >> 5, lane = t & 31;
    __shared__ __align__(16) float Hs[NPTS];
    const __half* Mbase = seg_M(seg);
    const float* rmin = dRmin[seg];
    const float C0Z = NEGLOGN * INVLN2f;
    int n = dNeps;

    // ---- init pass: eps0, H = log-weights only ----
    {
        float eps = dEps[0];
        float negs1 = -(1.f / eps) * INVLN2f;
        float el2 = eps * LN2f;
#pragma unroll
        for (int rp = 0; rp < 2; rp++) {
            int row0 = bb * 32 + rp * 16 + w * 2;
            float m0, s0, m1, s1;
            lse_pair<false>(Mbase + (size_t)row0 * NPTS, nullptr, negs1, m0, s0, m1, s1);
            if (lane == 0) {
                dF[0][seg][row0]     = rmin[row0]     - el2 * (m0 + lg2f_(s0));
                dF[0][seg][row0 + 1] = rmin[row0 + 1] - el2 * (m1 + lg2f_(s1));
            }
        }
    }
    grid_barrier();

    // ---- annealing loop: exactly n data-dependent iterations ----
    for (int it = 0; it < n; it++) {
        int src = it & 1, dst = src ^ 1;
        float eps = dEps[it];
        float s1f = (1.f / eps) * INVLN2f;
        const float* Hv = dF[src][hslot(seg)];
        for (int i = t * 4; i < NPTS; i += 1024) {
            float4 hv = *(const float4*)&Hv[i];
            float4 o;
            o.x = fmaf(hv.x, s1f, C0Z); o.y = fmaf(hv.y, s1f, C0Z);
            o.z = fmaf(hv.z, s1f, C0Z); o.w = fmaf(hv.w, s1f, C0Z);
            *(float4*)&Hs[i] = o;
        }
        __syncthreads();
        float el2 = eps * LN2f;
#pragma unroll
        for (int rp = 0; rp < 2; rp++) {
            int row0 = bb * 32 + rp * 16 + w * 2;
            float m0, s0, m1, s1;
            lse_pair<true>(Mbase + (size_t)row0 * NPTS, Hs, -s1f, m0, s0, m1, s1);
            if (lane == 0) {
                float ft0 = rmin[row0]     - el2 * (m0 + lg2f_(s0));
                float ft1 = rmin[row0 + 1] - el2 * (m1 + lg2f_(s1));
                dF[dst][seg][row0]     = 0.5f * (dF[src][seg][row0]     + ft0);
                dF[dst][seg][row0 + 1] = 0.5f * (dF[src][seg][row0 + 1] + ft1);
            }
        }
        grid_barrier();
    }

    // ---- final extrapolation at eps = BLUR^P ----
    {
        int src = n & 1;
        float eps = 0.0025f;
        float s1f = (1.f / eps) * INVLN2f;
        const float* Hv = dF[src][hslot(seg)];
        for (int i = t * 4; i < NPTS; i += 1024) {
            float4 hv = *(const float4*)&Hv[i];
            float4 o;
            o.x = fmaf(hv.x, s1f, C0Z); o.y = fmaf(hv.y, s1f, C0Z);
            o.z = fmaf(hv.z, s1f, C0Z); o.w = fmaf(hv.w, s1f, C0Z);
            *(float4*)&Hs[i] = o;
        }
        __syncthreads();
        float el2 = eps * LN2f;
#pragma unroll
        for (int rp = 0; rp < 2; rp++) {
            int row0 = bb * 32 + rp * 16 + w * 2;
            float m0, s0, m1, s1;
            lse_pair<true>(Mbase + (size_t)row0 * NPTS, Hs, -s1f, m0, s0, m1, s1);
            if (lane == 0) {
                dFin[seg][row0]     = rmin[row0]     - el2 * (m0 + lg2f_(s0));
                dFin[seg][row0 + 1] = rmin[row0 + 1] - el2 * (m1 + lg2f_(s1));
            }
        }
    }
    grid_barrier();

    // ---- reduction by block 0 ----
    if (bid == 0) {
        float s = 0.f;
        for (int i = t; i < NPTS; i += 256)
            s += (dFin[0][i] - dFin[2][i]) + (dFin[1][i] - dFin[3][i]);
#pragma unroll
        for (int o = 16; o; o >>= 1) s += __shfl_xor_sync(0xffffffffu, s, o);
        __shared__ float sm[8];
        if (lane == 0) sm[w] = s;
        __syncthreads();
        if (t == 0) {
            float tot = 0.f;
            for (int k = 0; k < 8; k++) tot += sm[k];
            out[0] = tot * (1.0f / NPTS);
        }
    }
}

// ---------------- launch ----------------
extern "C" void kernel_launch(void* const* d_in, const int* in_sizes, int n_in,
                              void* d_out, int out_size) {
    const float* x = (const float*)d_in[0];
    const float* y = (const float*)d_in[1];
    float* out = (float*)d_out;

    prep_k<<<128, 256>>>(x, y);                       // 1
    sched_k<<<1, 64>>>();                             // 2
    gemm_cost<<<3 * 1024, 256>>>(x, y);               // 3
    conv_straight_k<<<3 * 8192, 256>>>();             // 4
    conv_trans_k<<<128 * 128, dim3(32, 8)>>>();       // 5
    sinkhorn_k<<<NB, 256>>>(out);                     // 6  (ncu -s 5 profiles this)
}